// round 8
// baseline (speedup 1.0000x reference)
#include <cuda_runtime.h>
#include <cstdint>
#include <cstddef>

namespace {

constexpr int kB   = 4096;
constexpr int kN   = 64;
constexpr int kOBS = 192;
constexpr int kACT = 64;
constexpr int kIN  = 256;
constexpr int kD   = 128;
constexpr int kFH  = 64;
constexpr int kFO  = 64;

constexpr int kThreads = 512;  // 16 warps

// strides ≡ 8 (mod 32): conflict-free float2 (LDS.64) fragment loads
constexpr int SA_LD = 264;
constexpr int E_LD  = 136;
constexpr int S_LD  = 72;
constexpr int WG_LD = 40;

// SMEM pool (floats) — R6 plan, resized for new strides
constexpr int OFF_SA = 0;      // sa [64x264]=16896; later T + SC
constexpr int OFF_T  = 0;      // t [64x136]=8704; later H [64x72]
constexpr int OFF_SC = 8704;   // scores/weights [64x72]=4608 (8704+4608<=16896)
constexpr int OFF_H  = 0;
constexpr int OFF_E  = 16896;  // e, later x [64x136]=8704
constexpr int OFF_EQ = 25600;  // eq [64x136]=8704
constexpr int OFF_VT = 34304;  // v^T [128x72]=9216
constexpr int OFF_W0 = 43520;  // weight stage buf0 [128x40]=5120
constexpr int OFF_W1 = 48640;  // weight stage buf1 [128x40]=5120
constexpr int SMEM_FLOATS = 53760;
constexpr int SMEM_BYTES  = SMEM_FLOATS * 4;  // 215040

__device__ float gMt[kD * kD];  // gMt[j][i] = sum_d Wq[d][i]*Wk[d][j]

__device__ __forceinline__ float f2tf(float x) {
  uint32_t u;
  asm("cvt.rna.tf32.f32 %0, %1;" : "=r"(u) : "f"(x));
  return __uint_as_float(u);
}

// k-packing within 8-groups: logical k -> packed pos, (k, k+4) made adjacent.
// k&7: 0,1,2,3,4,5,6,7 -> 0,2,4,6,1,3,5,7
__device__ __forceinline__ int pk(int k) {
  return (k & ~7) + 2 * (k & 3) + ((k >> 2) & 1);
}

__device__ __forceinline__ void mma8(float (&d)[4], const uint32_t (&a)[4],
                                     const uint32_t (&b)[2]) {
  asm volatile(
      "mma.sync.aligned.m16n8k8.row.col.f32.tf32.tf32.f32 "
      "{%0,%1,%2,%3}, {%4,%5,%6,%7}, {%8,%9}, {%0,%1,%2,%3};\n"
      : "+f"(d[0]), "+f"(d[1]), "+f"(d[2]), "+f"(d[3])
      : "r"(a[0]), "r"(a[1]), "r"(a[2]), "r"(a[3]), "r"(b[0]), "r"(b[1]));
}

// C[64 rows][NT*8 cols per warp] += A[64][KC] * B[cols][KC]^T
// A/B stored pk-packed along k; one float2 per fragment pair.
// v.x = logical k0+gc -> a[0]/b[0]; v.y = logical k0+gc+4 -> a[2]/b[1].
template <int NT, int KC>
__device__ __forceinline__ void mma_block(const float* __restrict__ As, int lda,
                                          const float* __restrict__ Bs, int ldb,
                                          float (&d)[2][NT][4],
                                          int lane, int wm, int wn) {
  const float* Aw = As + (wm * 32) * lda;
  const float* Bw = Bs + (wn * NT * 8) * ldb;
  const int gr = lane >> 2, gc = lane & 3;
#pragma unroll
  for (int k0 = 0; k0 < KC; k0 += 8) {
    uint32_t a[2][4];
#pragma unroll
    for (int mt = 0; mt < 2; mt++) {
      float2 v0 = *(const float2*)(Aw + (mt * 16 + gr) * lda + k0 + 2 * gc);
      float2 v1 = *(const float2*)(Aw + (mt * 16 + 8 + gr) * lda + k0 + 2 * gc);
      a[mt][0] = __float_as_uint(v0.x);
      a[mt][1] = __float_as_uint(v1.x);
      a[mt][2] = __float_as_uint(v0.y);
      a[mt][3] = __float_as_uint(v1.y);
    }
#pragma unroll
    for (int nt = 0; nt < NT; nt++) {
      float2 bv = *(const float2*)(Bw + (nt * 8 + gr) * ldb + k0 + 2 * gc);
      uint32_t bf[2] = {__float_as_uint(bv.x), __float_as_uint(bv.y)};
      mma8(d[0][nt], a[0], bf);
      mma8(d[1][nt], a[1], bf);
    }
  }
}

template <int NT, class F>
__device__ __forceinline__ void for_each(float (&d)[2][NT][4], int lane,
                                         int wm, int wn, F f) {
  const int gr = lane >> 2, gc = (lane & 3) * 2;
#pragma unroll
  for (int mt = 0; mt < 2; mt++)
#pragma unroll
    for (int nt = 0; nt < NT; nt++)
#pragma unroll
      for (int i = 0; i < 4; i++) {
        int row = wm * 32 + mt * 16 + gr + ((i >> 1) << 3);
        int col = wn * NT * 8 + nt * 8 + gc + (i & 1);
        f(row, col, d[mt][nt][i]);
      }
}

template <int NT>
__device__ __forceinline__ void zero_acc(float (&d)[2][NT][4]) {
#pragma unroll
  for (int mt = 0; mt < 2; mt++)
#pragma unroll
    for (int nt = 0; nt < NT; nt++)
#pragma unroll
      for (int i = 0; i < 4; i++) d[mt][nt][i] = 0.f;
}

// ---- weight chunk staging (R6 verbatim, STS address pk-packed)
__device__ __forceinline__ void ldg_chunk(float (&r)[8], const float* __restrict__ W,
                                          int On, int Kfull, int k0, int tid) {
  const int total = On * 32;
#pragma unroll
  for (int j = 0; j < 8; j++) {
    int i = tid + j * kThreads;
    if (i < total) {
      int o = i >> 5, k = i & 31;
      r[j] = __ldg(W + o * Kfull + k0 + k);
    }
  }
}

__device__ __forceinline__ void sts_chunk(float* buf, const float (&r)[8],
                                          int On, int tid) {
  const int total = On * 32;
#pragma unroll
  for (int j = 0; j < 8; j++) {
    int i = tid + j * kThreads;
    if (i < total) {
      int o = i >> 5, k = i & 31;
      buf[o * WG_LD + pk(k)] = f2tf(r[j]);
    }
  }
}

// Double-buffered staged matmul (R6 verbatim structure; mma guarded by
// `active`; all barriers outside the conditional).
template <int NT, int NCH>
__device__ __forceinline__ void staged_mm(const float* __restrict__ A, int lda,
                                          const float* __restrict__ W, int On,
                                          int Kfull, int kbase,
                                          float (&d)[2][NT][4],
                                          float* wg0, float* wg1, int tid,
                                          int lane, int wm, int wn,
                                          bool active) {
  float r[8];
  ldg_chunk(r, W, On, Kfull, kbase, tid);
  sts_chunk(wg0, r, On, tid);
  __syncthreads();
#pragma unroll
  for (int c = 0; c < NCH; c++) {
    float* cur = (c & 1) ? wg1 : wg0;
    float* nxt = (c & 1) ? wg0 : wg1;
    const bool more = (c + 1 < NCH);
    if (more) ldg_chunk(r, W, On, Kfull, kbase + (c + 1) * 32, tid);
    if (active) mma_block<NT, 32>(A + c * 32, lda, cur, WG_LD, d, lane, wm, wn);
    if (more) sts_chunk(nxt, r, On, tid);
    __syncthreads();
  }
}

// ---- prologue: gMt[j][i] = sum_d Wq[d][i]*Wk[d][j]
__global__ void precompute_mt(const float* __restrict__ Wq,
                              const float* __restrict__ Wk) {
  __shared__ float wkj[kD];
  const int j = blockIdx.x;
  const int i = threadIdx.x;
  wkj[i] = Wk[i * kD + j];
  __syncthreads();
  float s = 0.f;
#pragma unroll 8
  for (int dd = 0; dd < kD; dd++) s += Wq[dd * kD + i] * wkj[dd];
  gMt[j * kD + i] = s;
}

__global__ __launch_bounds__(kThreads, 1)
void critic_kernel(const float* __restrict__ states,
                   const float* __restrict__ actions,
                   const float* __restrict__ W_embed,
                   const float* __restrict__ b_embed,
                   const float* __restrict__ W_v,
                   const float* __restrict__ W_embed_q,
                   const float* __restrict__ b_embed_q,
                   const float* __restrict__ W_f1,
                   const float* __restrict__ W_f2,
                   float* __restrict__ outV,
                   float* __restrict__ outW) {
  extern __shared__ float smem[];
  const int b = blockIdx.x;
  const int tid = threadIdx.x;
  const int lane = tid & 31;
  const int warp = tid >> 5;
  // 16-warp grid (scores/x/f1/Value stages)
  const int wm16 = warp >> 3, wn16 = warp & 7;
  // 8-warp grid with 32x32 tiles (e/eq/t/v stages)
  const int wm8 = (warp >> 2) & 1, wn8 = warp & 3;
  const bool act8 = (warp < 8);

  float* SA = smem + OFF_SA;
  float* T  = smem + OFF_T;
  float* SC = smem + OFF_SC;
  float* H  = smem + OFF_H;
  float* E  = smem + OFF_E;
  float* EQ = smem + OFF_EQ;
  float* VT = smem + OFF_VT;
  float* W0 = smem + OFF_W0;
  float* W1 = smem + OFF_W1;

  // ---- load sa, pk-packed (visibility covered by first staged_mm barrier)
  {
    const float* st = states + (size_t)b * kN * kOBS;
    const float* ac = actions + (size_t)b * kN * kACT;
#pragma unroll 4
    for (int j = 0; j < 32; j++) {
      int i = tid + j * kThreads;
      int t = i >> 8, c = i & 255;
      float v = (c < kOBS) ? st[t * kOBS + c] : ac[t * kACT + (c - kOBS)];
      SA[t * SA_LD + pk(c)] = f2tf(v);
    }
  }

  float d4[2][4][4];
  float d2[2][2][4];
  float d1[2][1][4];

  // ---- e = lrelu(sa @ W_embed^T + b_embed)  [64,128]  (warps 0-7, 32x32)
  zero_acc(d4);
  staged_mm<4, 8>(SA, SA_LD, W_embed, 128, kIN, 0, d4, W0, W1, tid, lane,
                  wm8, wn8, act8);
  if (act8)
    for_each<4>(d4, lane, wm8, wn8, [&](int r, int c, float v) {
      v += __ldg(b_embed + c);
      v = v > 0.f ? v : 0.01f * v;
      E[r * E_LD + pk(c)] = f2tf(v);
    });

  // ---- eq = lrelu(sa @ W_embed_q^T + b_embed_q)  [64,128]
  zero_acc(d4);
  staged_mm<4, 8>(SA, SA_LD, W_embed_q, 128, kIN, 0, d4, W0, W1, tid, lane,
                  wm8, wn8, act8);
  if (act8)
    for_each<4>(d4, lane, wm8, wn8, [&](int r, int c, float v) {
      v += __ldg(b_embed_q + c);
      v = v > 0.f ? v : 0.01f * v;
      EQ[r * E_LD + pk(c)] = f2tf(v);
    });
  __syncthreads();  // SA fully dead; T may now alias it

  // ---- t = e @ Mt^T  [64,128]
  zero_acc(d4);
  staged_mm<4, 4>(E, E_LD, gMt, 128, kD, 0, d4, W0, W1, tid, lane,
                  wm8, wn8, act8);
  if (act8)
    for_each<4>(d4, lane, wm8, wn8, [&](int r, int c, float v) {
      T[r * E_LD + pk(c)] = f2tf(v);
    });

  // ---- v = e @ W_v^T, stored transposed VT[d][m], token-dim packed
  zero_acc(d4);
  staged_mm<4, 4>(E, E_LD, W_v, 128, kD, 0, d4, W0, W1, tid, lane,
                  wm8, wn8, act8);
  if (act8)
    for_each<4>(d4, lane, wm8, wn8, [&](int r, int c, float v) {
      VT[c * S_LD + pk(r)] = f2tf(v);
    });
  __syncthreads();  // T, VT visible to all warps

  // ---- scores = t @ e^T / sqrt(D)  [64,64] -> SC unpacked fp32 (16 warps)
  zero_acc(d1);
  mma_block<1, 128>(T, E_LD, E, E_LD, d1, lane, wm16, wn16);
  for_each<1>(d1, lane, wm16, wn16, [&](int r, int c, float v) {
    SC[r * S_LD + c] = v * 0.08838834764831845f;
  });
  __syncthreads();

  // ---- row softmax: gmem fp32 (logical order) + packed tf32 back into SC
  {
    const int r = tid >> 3;
    const int c0 = (tid & 7) * 8;  // 8-aligned -> in-group packing valid
    float* wrow = SC + r * S_LD + c0;
    float s[8];
#pragma unroll
    for (int j = 0; j < 8; j++) s[j] = wrow[j];
    float mx = -3.0e38f;
#pragma unroll
    for (int j = 0; j < 8; j++) mx = fmaxf(mx, s[j]);
    mx = fmaxf(mx, __shfl_xor_sync(0xffffffffu, mx, 1));
    mx = fmaxf(mx, __shfl_xor_sync(0xffffffffu, mx, 2));
    mx = fmaxf(mx, __shfl_xor_sync(0xffffffffu, mx, 4));
    float sum = 0.f;
#pragma unroll
    for (int j = 0; j < 8; j++) {
      s[j] = __expf(s[j] - mx);
      sum += s[j];
    }
    sum += __shfl_xor_sync(0xffffffffu, sum, 1);
    sum += __shfl_xor_sync(0xffffffffu, sum, 2);
    sum += __shfl_xor_sync(0xffffffffu, sum, 4);
    float inv = 1.f / sum;
    float* og = outW + ((size_t)b * kN + r) * kN + c0;
#pragma unroll
    for (int j = 0; j < 8; j++) {
      float wv = s[j] * inv;
      og[j] = wv;
      wrow[2 * (j & 3) + (j >> 2)] = f2tf(wv);  // pk within the 8-group
    }
  }
  __syncthreads();

  // ---- x = weight @ v  [64,128]  (16 warps) -> E region (e is dead)
  zero_acc(d2);
  mma_block<2, 64>(SC, S_LD, VT, S_LD, d2, lane, wm16, wn16);
  for_each<2>(d2, lane, wm16, wn16, [&](int r, int c, float v) {
    E[r * E_LD + pk(c)] = f2tf(v);
  });
  __syncthreads();

  // ---- h = lrelu([eq, x] @ W_f1^T)  [64,64]  (16 warps, accumulate halves)
  zero_acc(d1);
  staged_mm<1, 4>(EQ, E_LD, W_f1, 64, 2 * kD, 0, d1, W0, W1, tid, lane,
                  wm16, wn16, true);
  staged_mm<1, 4>(E, E_LD, W_f1, 64, 2 * kD, kD, d1, W0, W1, tid, lane,
                  wm16, wn16, true);
  for_each<1>(d1, lane, wm16, wn16, [&](int r, int c, float v) {
    v = v > 0.f ? v : 0.01f * v;
    H[r * S_LD + pk(c)] = f2tf(v);
  });

  // ---- Value = h @ W_f2^T -> gmem (staged_mm's first barrier covers H)
  zero_acc(d1);
  staged_mm<1, 2>(H, S_LD, W_f2, 64, kFH, 0, d1, W0, W1, tid, lane,
                  wm16, wn16, true);
  for_each<1>(d1, lane, wm16, wn16, [&](int r, int c, float v) {
    outV[((size_t)b * kN + r) * kFO + c] = v;
  });
}

}  // namespace

extern "C" void kernel_launch(void* const* d_in, const int* in_sizes, int n_in,
                              void* d_out, int out_size) {
  (void)in_sizes; (void)n_in; (void)out_size;
  const float* states    = (const float*)d_in[0];
  const float* actions   = (const float*)d_in[1];
  const float* W_embed   = (const float*)d_in[2];
  const float* b_embed   = (const float*)d_in[3];
  const float* W_k       = (const float*)d_in[4];
  const float* W_q       = (const float*)d_in[5];
  const float* W_v       = (const float*)d_in[6];
  const float* W_embed_q = (const float*)d_in[7];
  const float* b_embed_q = (const float*)d_in[8];
  const float* W_f1      = (const float*)d_in[9];
  const float* W_f2      = (const float*)d_in[10];

  float* outV = (float*)d_out;                 // Value [B,N,64]
  float* outW = outV + (size_t)kB * kN * kFO;  // weight [B,N,N]

  precompute_mt<<<kD, kD>>>(W_q, W_k);

  cudaFuncSetAttribute(critic_kernel,
                       cudaFuncAttributeMaxDynamicSharedMemorySize, SMEM_BYTES);
  critic_kernel<<<kB, kThreads, SMEM_BYTES>>>(states, actions, W_embed,
                                              b_embed, W_v, W_embed_q,
                                              b_embed_q, W_f1, W_f2,
                                              outV, outW);
}

// round 9
// speedup vs baseline: 1.0538x; 1.0538x over previous
#include <cuda_runtime.h>
#include <cstdint>
#include <cstddef>

namespace {

constexpr int kB   = 4096;
constexpr int kN   = 64;
constexpr int kOBS = 192;
constexpr int kACT = 64;
constexpr int kIN  = 256;
constexpr int kD   = 128;
constexpr int kFH  = 64;
constexpr int kFO  = 64;

constexpr int kThreads = 512;  // 16 warps

// strides ≡ 8 (mod 32): conflict-free float2 fragment loads (R8-proven)
constexpr int SA_LD = 264;
constexpr int E_LD  = 136;
constexpr int S_LD  = 72;
constexpr int WG_LD = 40;

// SMEM pool (floats) — R8 plan
constexpr int OFF_SA = 0;      // sa [64x264]=16896; later T + SC
constexpr int OFF_T  = 0;      // t [64x136]=8704; later H [64x72]
constexpr int OFF_SC = 8704;   // scores/weights [64x72]=4608
constexpr int OFF_H  = 0;
constexpr int OFF_E  = 16896;  // e, later x [64x136]=8704
constexpr int OFF_EQ = 25600;  // eq [64x136]=8704
constexpr int OFF_VT = 34304;  // v^T [128x72]=9216
constexpr int OFF_W0 = 43520;  // weight stage buf0 [128x40]=5120
constexpr int OFF_W1 = 48640;  // weight stage buf1 [128x40]=5120
constexpr int SMEM_FLOATS = 53760;
constexpr int SMEM_BYTES  = SMEM_FLOATS * 4;  // 215040

__device__ float gMt[kD * kD];  // gMt[j][i] = sum_d Wq[d][i]*Wk[d][j]

__device__ __forceinline__ float f2tf(float x) {
  uint32_t u;
  asm("cvt.rna.tf32.f32 %0, %1;" : "=r"(u) : "f"(x));
  return __uint_as_float(u);
}

// packing within 8-groups: logical k -> packed pos (k,k+4) adjacent.
__device__ __forceinline__ int pk(int k) {
  return (k & ~7) + 2 * (k & 3) + ((k >> 2) & 1);
}

__device__ __forceinline__ void mma8(float (&d)[4], const uint32_t (&a)[4],
                                     const uint32_t (&b)[2]) {
  asm volatile(
      "mma.sync.aligned.m16n8k8.row.col.f32.tf32.tf32.f32 "
      "{%0,%1,%2,%3}, {%4,%5,%6,%7}, {%8,%9}, {%0,%1,%2,%3};\n"
      : "+f"(d[0]), "+f"(d[1]), "+f"(d[2]), "+f"(d[3])
      : "r"(a[0]), "r"(a[1]), "r"(a[2]), "r"(a[3]), "r"(b[0]), "r"(b[1]));
}

// R8-proven float2 fragment loads; A/B pk-packed along k.
template <int NT, int KC>
__device__ __forceinline__ void mma_block(const float* __restrict__ As, int lda,
                                          const float* __restrict__ Bs, int ldb,
                                          float (&d)[2][NT][4],
                                          int lane, int wm, int wn) {
  const float* Aw = As + (wm * 32) * lda;
  const float* Bw = Bs + (wn * NT * 8) * ldb;
  const int gr = lane >> 2, gc = lane & 3;
#pragma unroll
  for (int k0 = 0; k0 < KC; k0 += 8) {
    uint32_t a[2][4];
#pragma unroll
    for (int mt = 0; mt < 2; mt++) {
      float2 v0 = *(const float2*)(Aw + (mt * 16 + gr) * lda + k0 + 2 * gc);
      float2 v1 = *(const float2*)(Aw + (mt * 16 + 8 + gr) * lda + k0 + 2 * gc);
      a[mt][0] = __float_as_uint(v0.x);
      a[mt][1] = __float_as_uint(v1.x);
      a[mt][2] = __float_as_uint(v0.y);
      a[mt][3] = __float_as_uint(v1.y);
    }
#pragma unroll
    for (int nt = 0; nt < NT; nt++) {
      float2 bv = *(const float2*)(Bw + (nt * 8 + gr) * ldb + k0 + 2 * gc);
      uint32_t bf[2] = {__float_as_uint(bv.x), __float_as_uint(bv.y)};
      mma8(d[0][nt], a[0], bf);
      mma8(d[1][nt], a[1], bf);
    }
  }
}

// Pair-wise epilogue: f(row, cphys, d_lo, d_hi) for the float2 at physical
// columns (cphys, cphys+1). With row-permuted B staging these hold logical
// (g, g+4) and cphys IS the packed destination index (identity).
template <int NT, class F>
__device__ __forceinline__ void for_each_pair(float (&d)[2][NT][4], int lane,
                                              int wm, int wn, F f) {
  const int gr = lane >> 2;
  const int gc2 = (lane & 3) * 2;
#pragma unroll
  for (int mt = 0; mt < 2; mt++)
#pragma unroll
    for (int nt = 0; nt < NT; nt++) {
      int col = wn * NT * 8 + nt * 8 + gc2;
      int row = wm * 32 + mt * 16 + gr;
      f(row, col, d[mt][nt][0], d[mt][nt][1]);
      f(row + 8, col, d[mt][nt][2], d[mt][nt][3]);
    }
}

template <int NT>
__device__ __forceinline__ void zero_acc(float (&d)[2][NT][4]) {
#pragma unroll
  for (int mt = 0; mt < 2; mt++)
#pragma unroll
    for (int nt = 0; nt < NT; nt++)
#pragma unroll
      for (int i = 0; i < 4; i++) d[mt][nt][i] = 0.f;
}

// ---- weight chunk staging. RPERM: place logical row o at pk8(o) within its
// 8-row group (permutes MMA output cols so epilogue packing is identity).
// Both perms hoist: (i&31) and ((i>>5)&7) are j-invariant for stride-512 i.
__device__ __forceinline__ void ldg_chunk(float (&r)[8], const float* __restrict__ W,
                                          int On, int Kfull, int k0, int tid) {
  const int total = On * 32;
#pragma unroll
  for (int j = 0; j < 8; j++) {
    int i = tid + j * kThreads;
    if (i < total) {
      int o = i >> 5, k = i & 31;
      r[j] = __ldg(W + o * Kfull + k0 + k);
    }
  }
}

template <bool RPERM>
__device__ __forceinline__ void sts_chunk(float* buf, const float (&r)[8],
                                          int On, int tid) {
  const int total = On * 32;
#pragma unroll
  for (int j = 0; j < 8; j++) {
    int i = tid + j * kThreads;
    if (i < total) {
      int o = i >> 5, k = i & 31;
      int op = RPERM ? pk(o) : o;
      buf[op * WG_LD + pk(k)] = f2tf(r[j]);
    }
  }
}

// Single-sync double-buffered staged matmul (R7-proven pattern).
// Iter c: ldg(c+1) | mma(cur) | sts(nxt) | sync.
template <int NT, int NCH, bool RPERM>
__device__ __forceinline__ void staged_mm(const float* __restrict__ A, int lda,
                                          const float* __restrict__ W, int On,
                                          int Kfull, int kbase,
                                          float (&d)[2][NT][4],
                                          float* wg0, float* wg1, int tid,
                                          int lane, int wm, int wn,
                                          bool active) {
  float r[8];
  ldg_chunk(r, W, On, Kfull, kbase, tid);
  sts_chunk<RPERM>(wg0, r, On, tid);
  __syncthreads();
#pragma unroll
  for (int c = 0; c < NCH; c++) {
    float* cur = (c & 1) ? wg1 : wg0;
    float* nxt = (c & 1) ? wg0 : wg1;
    const bool more = (c + 1 < NCH);
    if (more) ldg_chunk(r, W, On, Kfull, kbase + (c + 1) * 32, tid);
    if (active) mma_block<NT, 32>(A + c * 32, lda, cur, WG_LD, d, lane, wm, wn);
    if (more) sts_chunk<RPERM>(nxt, r, On, tid);
    __syncthreads();
  }
}

// ---- prologue: gMt[j][i] = sum_d Wq[d][i]*Wk[d][j]
__global__ void precompute_mt(const float* __restrict__ Wq,
                              const float* __restrict__ Wk) {
  __shared__ float wkj[kD];
  const int j = blockIdx.x;
  const int i = threadIdx.x;
  wkj[i] = Wk[i * kD + j];
  __syncthreads();
  float s = 0.f;
#pragma unroll 8
  for (int dd = 0; dd < kD; dd++) s += Wq[dd * kD + i] * wkj[dd];
  gMt[j * kD + i] = s;
}

__global__ __launch_bounds__(kThreads, 1)
void critic_kernel(const float* __restrict__ states,
                   const float* __restrict__ actions,
                   const float* __restrict__ W_embed,
                   const float* __restrict__ b_embed,
                   const float* __restrict__ W_v,
                   const float* __restrict__ W_embed_q,
                   const float* __restrict__ b_embed_q,
                   const float* __restrict__ W_f1,
                   const float* __restrict__ W_f2,
                   float* __restrict__ outV,
                   float* __restrict__ outW) {
  extern __shared__ float smem[];
  const int b = blockIdx.x;
  const int tid = threadIdx.x;
  const int lane = tid & 31;
  const int warp = tid >> 5;
  const int wm16 = warp >> 3, wn16 = warp & 7;          // 16-warp grid
  const int wm8 = (warp >> 2) & 1, wn8 = warp & 3;      // 8-warp 32x32 grid
  const bool act8 = (warp < 8);
  const int gr = lane >> 2;
  const int pkgr = 2 * (gr & 3) + ((gr >> 2) & 1);      // pk8 of gr (hoisted)

  float* SA = smem + OFF_SA;
  float* T  = smem + OFF_T;
  float* SC = smem + OFF_SC;
  float* H  = smem + OFF_H;
  float* E  = smem + OFF_E;
  float* EQ = smem + OFF_EQ;
  float* VT = smem + OFF_VT;
  float* W0 = smem + OFF_W0;
  float* W1 = smem + OFF_W1;

  // ---- load sa, pk-packed (pk hoists: c&7 = tid&7); first staged sync covers
  {
    const float* st = states + (size_t)b * kN * kOBS;
    const float* ac = actions + (size_t)b * kN * kACT;
#pragma unroll 4
    for (int j = 0; j < 32; j++) {
      int i = tid + j * kThreads;
      int t = i >> 8, c = i & 255;
      float v = (c < kOBS) ? st[t * kOBS + c] : ac[t * kACT + (c - kOBS)];
      SA[t * SA_LD + pk(c)] = f2tf(v);
    }
  }

  float d4[2][4][4];
  float d2[2][2][4];
  float d1[2][1][4];

  // ---- e = lrelu(sa @ W_embed^T + b)  (warps 0-7, 32x32; RPERM staging)
  zero_acc(d4);
  staged_mm<4, 8, true>(SA, SA_LD, W_embed, 128, kIN, 0, d4, W0, W1, tid, lane,
                        wm8, wn8, act8);
  if (act8)
    for_each_pair<4>(d4, lane, wm8, wn8, [&](int r, int c, float lo, float hi) {
      int lg = (c & ~7) + ((c & 7) >> 1);  // logical col of lo; hi = lg+4
      lo += __ldg(b_embed + lg);
      hi += __ldg(b_embed + lg + 4);
      lo = lo > 0.f ? lo : 0.01f * lo;
      hi = hi > 0.f ? hi : 0.01f * hi;
      *(float2*)(E + r * E_LD + c) = make_float2(f2tf(lo), f2tf(hi));
    });

  // ---- eq = lrelu(sa @ W_embed_q^T + b_q)
  zero_acc(d4);
  staged_mm<4, 8, true>(SA, SA_LD, W_embed_q, 128, kIN, 0, d4, W0, W1, tid,
                        lane, wm8, wn8, act8);
  if (act8)
    for_each_pair<4>(d4, lane, wm8, wn8, [&](int r, int c, float lo, float hi) {
      int lg = (c & ~7) + ((c & 7) >> 1);
      lo += __ldg(b_embed_q + lg);
      hi += __ldg(b_embed_q + lg + 4);
      lo = lo > 0.f ? lo : 0.01f * lo;
      hi = hi > 0.f ? hi : 0.01f * hi;
      *(float2*)(EQ + r * E_LD + c) = make_float2(f2tf(lo), f2tf(hi));
    });
  __syncthreads();  // SA fully dead; T may alias

  // ---- t = e @ Mt^T  (identity-packed epilogue)
  zero_acc(d4);
  staged_mm<4, 4, true>(E, E_LD, gMt, 128, kD, 0, d4, W0, W1, tid, lane,
                        wm8, wn8, act8);
  if (act8)
    for_each_pair<4>(d4, lane, wm8, wn8, [&](int r, int c, float lo, float hi) {
      *(float2*)(T + r * E_LD + c) = make_float2(f2tf(lo), f2tf(hi));
    });

  // ---- v = e @ W_v^T, transposed into VT[dphys][token-packed]
  zero_acc(d4);
  staged_mm<4, 4, true>(E, E_LD, W_v, 128, kD, 0, d4, W0, W1, tid, lane,
                        wm8, wn8, act8);
  if (act8)
    for_each_pair<4>(d4, lane, wm8, wn8, [&](int r, int c, float lo, float hi) {
      int rp = (r & ~7) + pkgr;  // packed token index (hoisted pk of r&7=gr)
      VT[c * S_LD + rp] = f2tf(lo);
      VT[(c + 1) * S_LD + rp] = f2tf(hi);
    });
  __syncthreads();  // T, VT visible

  // ---- scores = t @ e^T / sqrt(D) -> SC (plain fp32; cols logical since E
  //      rows are unpermuted tokens)  (16 warps)
  zero_acc(d1);
  mma_block<1, 128>(T, E_LD, E, E_LD, d1, lane, wm16, wn16);
  for_each_pair<1>(d1, lane, wm16, wn16, [&](int r, int c, float lo, float hi) {
    *(float2*)(SC + r * S_LD + c) =
        make_float2(lo * 0.08838834764831845f, hi * 0.08838834764831845f);
  });
  __syncthreads();

  // ---- row softmax: gmem fp32 logical + packed tf32 into SC (indices
  //      compile-time in the unrolled loop)
  {
    const int r = tid >> 3;
    const int c0 = (tid & 7) * 8;
    float* wrow = SC + r * S_LD + c0;
    float s[8];
#pragma unroll
    for (int j = 0; j < 8; j++) s[j] = wrow[j];
    float mx = -3.0e38f;
#pragma unroll
    for (int j = 0; j < 8; j++) mx = fmaxf(mx, s[j]);
    mx = fmaxf(mx, __shfl_xor_sync(0xffffffffu, mx, 1));
    mx = fmaxf(mx, __shfl_xor_sync(0xffffffffu, mx, 2));
    mx = fmaxf(mx, __shfl_xor_sync(0xffffffffu, mx, 4));
    float sum = 0.f;
#pragma unroll
    for (int j = 0; j < 8; j++) {
      s[j] = __expf(s[j] - mx);
      sum += s[j];
    }
    sum += __shfl_xor_sync(0xffffffffu, sum, 1);
    sum += __shfl_xor_sync(0xffffffffu, sum, 2);
    sum += __shfl_xor_sync(0xffffffffu, sum, 4);
    float inv = 1.f / sum;
    float* og = outW + ((size_t)b * kN + r) * kN + c0;
#pragma unroll
    for (int j = 0; j < 8; j++) {
      float wv = s[j] * inv;
      og[j] = wv;
      wrow[2 * (j & 3) + (j >> 2)] = f2tf(wv);
    }
  }
  __syncthreads();

  // ---- x = weight @ v -> E (VT rows are physical == packed-identity cols)
  zero_acc(d2);
  mma_block<2, 64>(SC, S_LD, VT, S_LD, d2, lane, wm16, wn16);
  for_each_pair<2>(d2, lane, wm16, wn16, [&](int r, int c, float lo, float hi) {
    *(float2*)(E + r * E_LD + c) = make_float2(f2tf(lo), f2tf(hi));
  });
  __syncthreads();

  // ---- h = lrelu([eq, x] @ W_f1^T)  (16 warps, accumulate halves)
  zero_acc(d1);
  staged_mm<1, 4, true>(EQ, E_LD, W_f1, 64, 2 * kD, 0, d1, W0, W1, tid, lane,
                        wm16, wn16, true);
  staged_mm<1, 4, true>(E, E_LD, W_f1, 64, 2 * kD, kD, d1, W0, W1, tid, lane,
                        wm16, wn16, true);
  for_each_pair<1>(d1, lane, wm16, wn16, [&](int r, int c, float lo, float hi) {
    lo = lo > 0.f ? lo : 0.01f * lo;
    hi = hi > 0.f ? hi : 0.01f * hi;
    *(float2*)(H + r * S_LD + c) = make_float2(f2tf(lo), f2tf(hi));
  });

  // ---- Value = h @ W_f2^T -> gmem (W_f2 un-permuted -> logical cols)
  zero_acc(d1);
  staged_mm<1, 2, false>(H, S_LD, W_f2, 64, kFH, 0, d1, W0, W1, tid, lane,
                         wm16, wn16, true);
  for_each_pair<1>(d1, lane, wm16, wn16, [&](int r, int c, float lo, float hi) {
    *(float2*)(outV + ((size_t)b * kN + r) * kFO + c) = make_float2(lo, hi);
  });
}

}  // namespace

extern "C" void kernel_launch(void* const* d_in, const int* in_sizes, int n_in,
                              void* d_out, int out_size) {
  (void)in_sizes; (void)n_in; (void)out_size;
  const float* states    = (const float*)d_in[0];
  const float* actions   = (const float*)d_in[1];
  const float* W_embed   = (const float*)d_in[2];
  const float* b_embed   = (const float*)d_in[3];
  const float* W_k       = (const float*)d_in[4];
  const float* W_q       = (const float*)d_in[5];
  const float* W_v       = (const float*)d_in[6];
  const float* W_embed_q = (const float*)d_in[7];
  const float* b_embed_q = (const float*)d_in[8];
  const float* W_f1      = (const float*)d_in[9];
  const float* W_f2      = (const float*)d_in[10];

  float* outV = (float*)d_out;                 // Value [B,N,64]
  float* outW = outV + (size_t)kB * kN * kFO;  // weight [B,N,N]

  precompute_mt<<<kD, kD>>>(W_q, W_k);

  cudaFuncSetAttribute(critic_kernel,
                       cudaFuncAttributeMaxDynamicSharedMemorySize, SMEM_BYTES);
  critic_kernel<<<kB, kThreads, SMEM_BYTES>>>(states, actions, W_embed,
                                              b_embed, W_v, W_embed_q,
                                              b_embed_q, W_f1, W_f2,
                                              outV, outW);
}